// round 14
// baseline (speedup 1.0000x reference)
#include <cuda_runtime.h>
#include <cstdint>
#include <cmath>

// ---------------------------------------------------------------------------
// ResidualConvLSTM2D  (B=4, T=16, H=W=64, Cin=32, F=64)
// Round 13: R12 overlap + h-conv in high-parallelism config (32x16 tile,
// 2 px/thread, 2 CTAs/SM, 256 blocks/step) to shorten the serial chain.
// ---------------------------------------------------------------------------

#define B_   4
#define T_   16
#define WW   64
#define HW   4096
#define CIN_X 32
#define F_   64
#define COUT 256
#define FRAMES 64

typedef unsigned long long u64;

#define FMA_F32X2(d, a, b, c) \
    asm("fma.rn.f32x2 %0, %1, %2, %3;" : "=l"(d) : "l"(a), "l"(b), "l"(c))

__device__ __forceinline__ u64 bcast_f32x2(float v) {
    u64 r; unsigned u = __float_as_uint(v);
    asm("mov.b64 %0, {%1, %1};" : "=l"(r) : "r"(u));
    return r;
}
__device__ __forceinline__ void unpack_f32x2(u64 v, float& lo, float& hi) {
    unsigned a, b;
    asm("mov.b64 {%0, %1}, %2;" : "=r"(a), "=r"(b) : "l"(v));
    lo = __uint_as_float(a); hi = __uint_as_float(b);
}

// Scratch (allocation-free rule: __device__ globals)
__device__ float g_xplanar[FRAMES * CIN_X * HW];
__device__ float g_zx[FRAMES * COUT * HW];         // [frame][oc][pix]
__device__ float g_zs[B_ * COUT * HW];             // [b][oc][pix]
__device__ float g_h [B_ * F_ * HW];               // [b][f][pix]
__device__ float g_c [B_ * F_ * HW];               // [b][f][pix]

// ---------------------------------------------------------------------------
__global__ void zero_hc_kernel() {
    int g = blockIdx.x * 256 + threadIdx.x;
    if (g < B_ * F_ * HW) { g_h[g] = 0.f; g_c[g] = 0.f; }
}

// ---------------------------------------------------------------------------
__global__ void pack_x_kernel(const float* __restrict__ x) {
    __shared__ float s[256 * 33];
    int frame = blockIdx.y;
    int pix0  = blockIdx.x * 256;
    const float* src = x + (size_t)frame * (HW * CIN_X) + (size_t)pix0 * CIN_X;
    for (int i = threadIdx.x; i < 256 * CIN_X; i += 256) {
        int p = i >> 5, ci = i & 31;
        s[p * 33 + ci] = src[i];
    }
    __syncthreads();
    for (int i = threadIdx.x; i < 256 * CIN_X; i += 256) {
        int p = i & 255, ci = i >> 8;
        g_xplanar[((size_t)frame * CIN_X + ci) * HW + pix0 + p] = s[p * 33 + ci];
    }
}

// ---------------------------------------------------------------------------
__global__ void residual_kernel(const float* __restrict__ x,
                                const float* __restrict__ Wp,
                                const float* __restrict__ bp,
                                float* __restrict__ out) {
    __shared__ float sW[CIN_X * F_];
    __shared__ float sb[F_];
    for (int i = threadIdx.x; i < CIN_X * F_; i += 256) sW[i] = Wp[i];
    if (threadIdx.x < F_) sb[threadIdx.x] = bp[threadIdx.x];
    __syncthreads();

    int g = blockIdx.x * 256 + threadIdx.x;
    float xv[CIN_X];
    const float4* xp = (const float4*)(x + (size_t)g * CIN_X);
    #pragma unroll
    for (int i = 0; i < CIN_X / 4; i++) {
        float4 v = xp[i];
        xv[4*i] = v.x; xv[4*i+1] = v.y; xv[4*i+2] = v.z; xv[4*i+3] = v.w;
    }
    float* op = out + (size_t)g * F_;
    #pragma unroll 4
    for (int f = 0; f < F_; f++) {
        float a = sb[f];
        #pragma unroll
        for (int ci = 0; ci < CIN_X; ci++)
            a = fmaf(xv[ci], sW[ci * F_ + f], a);
        op[f] = a;
    }
}

// ---------------------------------------------------------------------------
// x-conv (MODE-0 style): tile 64x16, 4 px/thread, per-timestep slice.
// Runs on the main stream; hidden behind the recurrent chain.
// ---------------------------------------------------------------------------
#define IN_E (8 * 18 * 72)     // 10368 floats
#define W_E  (9 * 8 * 32)      // 2304 floats
#define IN_V4 (IN_E / 4)       // 2592
#define W_V4  (W_E / 4)        // 576
#define SMEM_CONV ((IN_E + W_E) * 4)   // 50688 B

__global__ __launch_bounds__(256, 1)
void conv_x_kernel(const float* __restrict__ wsrc, const float* __restrict__ bias,
                   int t) {
    extern __shared__ float sm[];
    float* s_in = sm;
    float* s_w  = sm + IN_E;

    int tileY = blockIdx.x;            // 0..3
    int frame = blockIdx.y * T_ + t;
    int oc0   = blockIdx.z * 32;
    int tid   = threadIdx.x;
    int tx = tid & 63, ty = tid >> 6;  // 64 x 4
    int gy0 = tileY * 16;

    const size_t in_base = ((size_t)frame * CIN_X) << 12;
    float4* s_in4 = (float4*)s_in;
    float4* s_w4  = (float4*)s_w;

    u64 acc[4][16];
    #pragma unroll
    for (int r = 0; r < 4; r++)
        #pragma unroll
        for (int i = 0; i < 16; i++) acc[r][i] = 0ull;

    for (int c0 = 0; c0 < CIN_X; c0 += 8) {
        #pragma unroll
        for (int it = 0; it < 11; it++) {
            int i = it * 256 + tid;
            if (it < 10 || i < IN_V4) {
                int seg = i % 18;
                int r   = i / 18;               // ci*18 + yy
                int yy  = r % 18, ci = r / 18;
                int gy  = gy0 + yy - 1;
                int gx  = -4 + seg * 4;
                float4 v = make_float4(0.f, 0.f, 0.f, 0.f);
                if (((unsigned)gy < 64u) & ((unsigned)gx <= 60u))
                    v = *(const float4*)(g_xplanar + in_base + (((size_t)(c0 + ci)) << 12) + gy * WW + gx);
                s_in4[r * 18 + seg] = v;
            }
        }
        #pragma unroll
        for (int it = 0; it < 3; it++) {
            int j = it * 256 + tid;
            if (it < 2 || j < W_V4) {
                int ocseg = j & 7;
                int tc    = j >> 3;
                int tap = tc >> 3, ci = tc & 7;
                s_w4[j] = *(const float4*)(wsrc + (size_t)(tap * CIN_X + c0 + ci) * COUT
                                           + oc0 + ocseg * 4);
            }
        }
        __syncthreads();

        #pragma unroll 1
        for (int tap = 0; tap < 9; tap++) {
            int dy = tap / 3, dx = tap - dy * 3;
            #pragma unroll
            for (int ci = 0; ci < 8; ci++) {
                u64 iv[4];
                #pragma unroll
                for (int r = 0; r < 4; r++)
                    iv[r] = bcast_f32x2(s_in[(ci * 18 + ty + 4 * r + dy) * 72 + tx + 3 + dx]);
                const ulonglong2* wp = (const ulonglong2*)&s_w[(tap * 8 + ci) * 32];
                #pragma unroll
                for (int j = 0; j < 8; j++) {
                    ulonglong2 w2 = wp[j];
                    #pragma unroll
                    for (int r = 0; r < 4; r++) {
                        FMA_F32X2(acc[r][2*j  ], iv[r], w2.x, acc[r][2*j  ]);
                        FMA_F32X2(acc[r][2*j+1], iv[r], w2.y, acc[r][2*j+1]);
                    }
                }
            }
        }
        __syncthreads();
    }

    size_t obase = ((size_t)frame * COUT + oc0) << 12;
    #pragma unroll
    for (int r = 0; r < 4; r++) {
        int p = (gy0 + ty + 4 * r) * WW + tx;
        #pragma unroll
        for (int j = 0; j < 16; j++) {
            float alo, ahi;
            unpack_f32x2(acc[r][j], alo, ahi);
            int oce = 2 * j, oco = 2 * j + 1;
            g_zx[obase + ((size_t)oce << 12) + p] = alo + bias[oc0 + oce];
            g_zx[obase + ((size_t)oco << 12) + p] = ahi + bias[oc0 + oco];
        }
    }
}

// ---------------------------------------------------------------------------
// h-conv: tile 32x16, 2 px/thread, 2 CTAs/SM, 256 blocks/step (critical path:
// maximize parallelism).  s_in [8 ci][18 rows][40 cols], col 0 = gx0-4.
// ---------------------------------------------------------------------------
#define HIN_E (8 * 18 * 40)     // 5760 floats
#define HIN_V4 (HIN_E / 4)      // 1440

__global__ __launch_bounds__(256, 2)
void conv_h_kernel(const float* __restrict__ wsrc) {
    __shared__ float s_in[HIN_E];
    __shared__ float s_w [W_E];

    int tileX = blockIdx.x & 1;
    int tileY = blockIdx.x >> 1;
    int b     = blockIdx.y;
    int oc0   = blockIdx.z * 32;
    int tid   = threadIdx.x;
    int tx = tid & 31, ty = tid >> 5;  // 32 x 8
    int gx0 = tileX * 32, gy0 = tileY * 16;

    const size_t in_base = ((size_t)b * F_) << 12;
    float4* s_in4 = (float4*)s_in;
    float4* s_w4  = (float4*)s_w;

    u64 acc0[16], acc1[16];
    #pragma unroll
    for (int i = 0; i < 16; i++) { acc0[i] = 0ull; acc1[i] = 0ull; }

    for (int c0 = 0; c0 < F_; c0 += 8) {
        #pragma unroll
        for (int it = 0; it < 6; it++) {
            int i = it * 256 + tid;
            if (it < 5 || i < HIN_V4) {
                int seg = i % 10;
                int r   = i / 10;               // ci*18 + yy
                int yy  = r % 18, ci = r / 18;
                int gy  = gy0 + yy - 1;
                int gx  = gx0 - 4 + seg * 4;
                float4 v = make_float4(0.f, 0.f, 0.f, 0.f);
                if (((unsigned)gy < 64u) & ((unsigned)gx <= 60u))
                    v = *(const float4*)(g_h + in_base + (((size_t)(c0 + ci)) << 12) + gy * WW + gx);
                s_in4[r * 10 + seg] = v;
            }
        }
        #pragma unroll
        for (int it = 0; it < 3; it++) {
            int j = it * 256 + tid;
            if (it < 2 || j < W_V4) {
                int ocseg = j & 7;
                int tc    = j >> 3;
                int tap = tc >> 3, ci = tc & 7;
                s_w4[j] = *(const float4*)(wsrc + (size_t)(tap * F_ + c0 + ci) * COUT
                                           + oc0 + ocseg * 4);
            }
        }
        __syncthreads();

        #pragma unroll 1
        for (int tap = 0; tap < 9; tap++) {
            int dy = tap / 3, dx = tap - dy * 3;
            #pragma unroll
            for (int ci = 0; ci < 8; ci++) {
                u64 i0 = bcast_f32x2(s_in[(ci * 18 + ty     + dy) * 40 + tx + 3 + dx]);
                u64 i1 = bcast_f32x2(s_in[(ci * 18 + ty + 8 + dy) * 40 + tx + 3 + dx]);
                const ulonglong2* wp = (const ulonglong2*)&s_w[(tap * 8 + ci) * 32];
                #pragma unroll
                for (int j = 0; j < 8; j++) {
                    ulonglong2 w2 = wp[j];
                    FMA_F32X2(acc0[2*j  ], i0, w2.x, acc0[2*j  ]);
                    FMA_F32X2(acc0[2*j+1], i0, w2.y, acc0[2*j+1]);
                    FMA_F32X2(acc1[2*j  ], i1, w2.x, acc1[2*j  ]);
                    FMA_F32X2(acc1[2*j+1], i1, w2.y, acc1[2*j+1]);
                }
            }
        }
        __syncthreads();
    }

    int p0 = (gy0 + ty) * WW + gx0 + tx;
    int p1 = p0 + 8 * WW;
    size_t obase = ((size_t)b * COUT + oc0) << 12;
    #pragma unroll
    for (int j = 0; j < 16; j++) {
        float a0lo, a0hi, a1lo, a1hi;
        unpack_f32x2(acc0[j], a0lo, a0hi);
        unpack_f32x2(acc1[j], a1lo, a1hi);
        int oce = 2 * j, oco = 2 * j + 1;
        g_zs[obase + ((size_t)oce << 12) + p0] = a0lo;
        g_zs[obase + ((size_t)oco << 12) + p0] = a0hi;
        g_zs[obase + ((size_t)oce << 12) + p1] = a1lo;
        g_zs[obase + ((size_t)oco << 12) + p1] = a1hi;
    }
}

// ---------------------------------------------------------------------------
// Gates + state + residual add (R2 mapping: 16 f per thread).
// ---------------------------------------------------------------------------
__global__ void gate_kernel(float* __restrict__ out, int t) {
    int g   = blockIdx.x * 256 + threadIdx.x;   // < 65536
    int q   = g & 3;
    int pix = (g >> 2) & 4095;
    int b   = g >> 14;
    int f0  = q * 16;
    int frame = b * T_ + t;

    size_t zxb = ((size_t)frame * COUT) << 12;
    size_t zsb = ((size_t)b * COUT) << 12;
    size_t cb  = ((size_t)b * F_)   << 12;
    float* op  = out + (((size_t)frame << 12) + pix) * F_;

    #pragma unroll
    for (int j = 0; j < 16; j++) {
        int f = f0 + j;
        float zi = g_zx[zxb + ((size_t)(f         ) << 12) + pix] + g_zs[zsb + ((size_t)(f         ) << 12) + pix];
        float zf = g_zx[zxb + ((size_t)(f +    F_ ) << 12) + pix] + g_zs[zsb + ((size_t)(f +    F_ ) << 12) + pix];
        float zc = g_zx[zxb + ((size_t)(f + 2 * F_) << 12) + pix] + g_zs[zsb + ((size_t)(f + 2 * F_) << 12) + pix];
        float zo = g_zx[zxb + ((size_t)(f + 3 * F_) << 12) + pix] + g_zs[zsb + ((size_t)(f + 3 * F_) << 12) + pix];

        float ig = __saturatef(fmaf(0.2f, zi, 0.5f));
        float fg = __saturatef(fmaf(0.2f, zf, 0.5f));
        float og = __saturatef(fmaf(0.2f, zo, 0.5f));

        float cold = g_c[cb + ((size_t)f << 12) + pix];
        float cnew = fmaf(fg, cold, ig * tanhf(zc));
        float h    = og * tanhf(cnew);

        g_c[cb + ((size_t)f << 12) + pix] = cnew;
        g_h[cb + ((size_t)f << 12) + pix] = h;
        op[f] = op[f] + h;
    }
}

// ---------------------------------------------------------------------------
extern "C" void kernel_launch(void* const* d_in, const int* in_sizes, int n_in,
                              void* d_out, int out_size) {
    const float* x  = (const float*)d_in[0];
    const float* Wx = (const float*)d_in[1];
    const float* Wh = (const float*)d_in[2];
    const float* b  = (const float*)d_in[3];
    const float* Wp = (const float*)d_in[4];
    const float* bp = (const float*)d_in[5];
    float* out = (float*)d_out;

    cudaFuncSetAttribute(conv_x_kernel,
                         cudaFuncAttributeMaxDynamicSharedMemorySize, SMEM_CONV);

    // side stream + events for overlap (host handles only; no device memory)
    cudaStream_t s1;
    cudaStreamCreateWithFlags(&s1, cudaStreamNonBlocking);
    cudaEvent_t ev[T_], evJoin;
    for (int t = 0; t < T_; t++) cudaEventCreateWithFlags(&ev[t], cudaEventDisableTiming);
    cudaEventCreateWithFlags(&evJoin, cudaEventDisableTiming);

    // main stream (0): state reset, pack, residual, then per-t x-conv slices
    zero_hc_kernel<<<(B_ * F_ * HW + 255) / 256, 256>>>();
    pack_x_kernel<<<dim3(16, FRAMES), 256>>>(x);
    residual_kernel<<<(FRAMES * HW) / 256, 256>>>(x, Wp, bp, out);

    for (int t = 0; t < T_; t++) {
        conv_x_kernel<<<dim3(4, B_, 8), 256, SMEM_CONV>>>(Wx, b, t);
        cudaEventRecord(ev[t], 0);
    }

    // side stream: recurrent chain, step t gated on its zx slice
    for (int t = 0; t < T_; t++) {
        cudaStreamWaitEvent(s1, ev[t], 0);
        conv_h_kernel<<<dim3(8, B_, 8), 256, 0, s1>>>(Wh);
        gate_kernel<<<256, 256, 0, s1>>>(out, t);
    }

    // join back to main stream
    cudaEventRecord(evJoin, s1);
    cudaStreamWaitEvent(0, evJoin, 0);
}

// round 15
// speedup vs baseline: 1.0948x; 1.0948x over previous
#include <cuda_runtime.h>
#include <cstdint>
#include <cmath>

// ---------------------------------------------------------------------------
// ResidualConvLSTM2D  (B=4, T=16, H=W=64, Cin=32, F=64)
// Round 14: R12 overlap champion + wavefront-optimal gate kernel
// (smem-transposed output RMW).
// ---------------------------------------------------------------------------

#define B_   4
#define T_   16
#define WW   64
#define HW   4096
#define CIN_X 32
#define F_   64
#define COUT 256
#define FRAMES 64

typedef unsigned long long u64;

#define FMA_F32X2(d, a, b, c) \
    asm("fma.rn.f32x2 %0, %1, %2, %3;" : "=l"(d) : "l"(a), "l"(b), "l"(c))

__device__ __forceinline__ u64 bcast_f32x2(float v) {
    u64 r; unsigned u = __float_as_uint(v);
    asm("mov.b64 %0, {%1, %1};" : "=l"(r) : "r"(u));
    return r;
}
__device__ __forceinline__ void unpack_f32x2(u64 v, float& lo, float& hi) {
    unsigned a, b;
    asm("mov.b64 {%0, %1}, %2;" : "=r"(a), "=r"(b) : "l"(v));
    lo = __uint_as_float(a); hi = __uint_as_float(b);
}

// Scratch (allocation-free rule: __device__ globals)
__device__ float g_xplanar[FRAMES * CIN_X * HW];
__device__ float g_zx[FRAMES * COUT * HW];         // [frame][oc][pix]
__device__ float g_zs[B_ * COUT * HW];             // [b][oc][pix]
__device__ float g_h [B_ * F_ * HW];               // [b][f][pix]
__device__ float g_c [B_ * F_ * HW];               // [b][f][pix]

// ---------------------------------------------------------------------------
__global__ void zero_hc_kernel() {
    int g = blockIdx.x * 256 + threadIdx.x;
    if (g < B_ * F_ * HW) { g_h[g] = 0.f; g_c[g] = 0.f; }
}

// ---------------------------------------------------------------------------
__global__ void pack_x_kernel(const float* __restrict__ x) {
    __shared__ float s[256 * 33];
    int frame = blockIdx.y;
    int pix0  = blockIdx.x * 256;
    const float* src = x + (size_t)frame * (HW * CIN_X) + (size_t)pix0 * CIN_X;
    for (int i = threadIdx.x; i < 256 * CIN_X; i += 256) {
        int p = i >> 5, ci = i & 31;
        s[p * 33 + ci] = src[i];
    }
    __syncthreads();
    for (int i = threadIdx.x; i < 256 * CIN_X; i += 256) {
        int p = i & 255, ci = i >> 8;
        g_xplanar[((size_t)frame * CIN_X + ci) * HW + pix0 + p] = s[p * 33 + ci];
    }
}

// ---------------------------------------------------------------------------
__global__ void residual_kernel(const float* __restrict__ x,
                                const float* __restrict__ Wp,
                                const float* __restrict__ bp,
                                float* __restrict__ out) {
    __shared__ float sW[CIN_X * F_];
    __shared__ float sb[F_];
    for (int i = threadIdx.x; i < CIN_X * F_; i += 256) sW[i] = Wp[i];
    if (threadIdx.x < F_) sb[threadIdx.x] = bp[threadIdx.x];
    __syncthreads();

    int g = blockIdx.x * 256 + threadIdx.x;
    float xv[CIN_X];
    const float4* xp = (const float4*)(x + (size_t)g * CIN_X);
    #pragma unroll
    for (int i = 0; i < CIN_X / 4; i++) {
        float4 v = xp[i];
        xv[4*i] = v.x; xv[4*i+1] = v.y; xv[4*i+2] = v.z; xv[4*i+3] = v.w;
    }
    float* op = out + (size_t)g * F_;
    #pragma unroll 4
    for (int f = 0; f < F_; f++) {
        float a = sb[f];
        #pragma unroll
        for (int ci = 0; ci < CIN_X; ci++)
            a = fmaf(xv[ci], sW[ci * F_ + f], a);
        op[f] = a;
    }
}

// ---------------------------------------------------------------------------
// 3x3 SAME conv, planar, FFMA2.  Tile 64x16, 4 px/thread, 32 oc/block.
// MODE 0: frame = blockIdx.y * 16 + t   (per-timestep x-conv slice -> g_zx)
// MODE 1: frame = blockIdx.y            (batch b, h-conv -> g_zs)
// ---------------------------------------------------------------------------
#define IN_E (8 * 18 * 72)     // 10368 floats
#define W_E  (9 * 8 * 32)      // 2304 floats
#define IN_V4 (IN_E / 4)       // 2592
#define W_V4  (W_E / 4)        // 576
#define SMEM_CONV ((IN_E + W_E) * 4)   // 50688 B

template<int CIN, int MODE>
__global__ __launch_bounds__(256, 1)
void conv3x3_kernel(const float* __restrict__ wsrc, const float* __restrict__ bias,
                    int t) {
    extern __shared__ float sm[];
    float* s_in = sm;
    float* s_w  = sm + IN_E;

    const float* in  = (MODE == 0) ? g_xplanar : g_h;
    float*       out = (MODE == 0) ? g_zx      : g_zs;

    int tileY = blockIdx.x;            // 0..3, 16 rows each
    int frame = (MODE == 0) ? (blockIdx.y * T_ + t) : blockIdx.y;
    int oc0   = blockIdx.z * 32;
    int tid   = threadIdx.x;
    int tx = tid & 63, ty = tid >> 6;  // 64 x 4
    int gy0 = tileY * 16;

    const size_t in_base = ((size_t)frame * CIN) << 12;
    float4* s_in4 = (float4*)s_in;
    float4* s_w4  = (float4*)s_w;

    u64 acc[4][16];
    #pragma unroll
    for (int r = 0; r < 4; r++)
        #pragma unroll
        for (int i = 0; i < 16; i++) acc[r][i] = 0ull;

    for (int c0 = 0; c0 < CIN; c0 += 8) {
        #pragma unroll
        for (int it = 0; it < 11; it++) {
            int i = it * 256 + tid;
            if (it < 10 || i < IN_V4) {
                int seg = i % 18;               // x = -4 + seg*4
                int r   = i / 18;               // ci*18 + yy
                int yy  = r % 18, ci = r / 18;
                int gy  = gy0 + yy - 1;
                int gx  = -4 + seg * 4;
                float4 v = make_float4(0.f, 0.f, 0.f, 0.f);
                if (((unsigned)gy < 64u) & ((unsigned)gx <= 60u))
                    v = *(const float4*)(in + in_base + (((size_t)(c0 + ci)) << 12) + gy * WW + gx);
                s_in4[r * 18 + seg] = v;
            }
        }
        #pragma unroll
        for (int it = 0; it < 3; it++) {
            int j = it * 256 + tid;
            if (it < 2 || j < W_V4) {
                int ocseg = j & 7;
                int tc    = j >> 3;             // tap*8 + ci
                int tap = tc >> 3, ci = tc & 7;
                s_w4[j] = *(const float4*)(wsrc + (size_t)(tap * CIN + c0 + ci) * COUT
                                           + oc0 + ocseg * 4);
            }
        }
        __syncthreads();

        #pragma unroll 1
        for (int tap = 0; tap < 9; tap++) {
            int dy = tap / 3, dx = tap - dy * 3;
            #pragma unroll
            for (int ci = 0; ci < 8; ci++) {
                u64 iv[4];
                #pragma unroll
                for (int r = 0; r < 4; r++)
                    iv[r] = bcast_f32x2(s_in[(ci * 18 + ty + 4 * r + dy) * 72 + tx + 3 + dx]);
                const ulonglong2* wp = (const ulonglong2*)&s_w[(tap * 8 + ci) * 32];
                #pragma unroll
                for (int j = 0; j < 8; j++) {
                    ulonglong2 w2 = wp[j];
                    #pragma unroll
                    for (int r = 0; r < 4; r++) {
                        FMA_F32X2(acc[r][2*j  ], iv[r], w2.x, acc[r][2*j  ]);
                        FMA_F32X2(acc[r][2*j+1], iv[r], w2.y, acc[r][2*j+1]);
                    }
                }
            }
        }
        __syncthreads();
    }

    size_t obase = ((size_t)frame * COUT + oc0) << 12;
    #pragma unroll
    for (int r = 0; r < 4; r++) {
        int p = (gy0 + ty + 4 * r) * WW + tx;
        #pragma unroll
        for (int j = 0; j < 16; j++) {
            float alo, ahi;
            unpack_f32x2(acc[r][j], alo, ahi);
            int oce = 2 * j, oco = 2 * j + 1;
            float bve = (MODE == 0) ? bias[oc0 + oce] : 0.f;
            float bvo = (MODE == 0) ? bias[oc0 + oco] : 0.f;
            out[obase + ((size_t)oce << 12) + p] = alo + bve;
            out[obase + ((size_t)oco << 12) + p] = ahi + bvo;
        }
    }
}

// ---------------------------------------------------------------------------
// Gates + state + residual add, two-phase with smem transpose.
// Block = 64 pixels x all 64 filters; grid 256 (= B*HW/64).
// Phase 1: thread (pl = tid&63, fg = tid>>6) computes 16 f for 1 pixel;
//          planar loads are lane-coalesced; h staged in sh[f][pl].
// Phase 2: thread (fq = tid&3, pl2 = tid>>2) does float4 RMW on
//          out[pix][f] -- sector-perfect writes.
// ---------------------------------------------------------------------------
__global__ void gate_kernel(float* __restrict__ out, int t) {
    __shared__ float sh[F_ * 65];               // [f][pix+pad]
    int blk = blockIdx.x;                        // 0..255
    int b   = blk >> 6;                          // 64 blocks per batch
    int pixbase = (blk & 63) * 64;
    int tid = threadIdx.x;
    int frame = b * T_ + t;

    {
        int pl = tid & 63;                       // lane-consecutive pixels
        int fg = tid >> 6;                       // 0..3 -> f0 = fg*16
        int pix = pixbase + pl;
        size_t zxb = (((size_t)frame * COUT) << 12) + pix;
        size_t zsb = (((size_t)b * COUT) << 12) + pix;
        size_t cb  = (((size_t)b * F_)   << 12) + pix;

        #pragma unroll
        for (int j = 0; j < 16; j++) {
            int f = fg * 16 + j;
            float zi = g_zx[zxb + ((size_t)(f         ) << 12)] + g_zs[zsb + ((size_t)(f         ) << 12)];
            float zf = g_zx[zxb + ((size_t)(f +    F_ ) << 12)] + g_zs[zsb + ((size_t)(f +    F_ ) << 12)];
            float zc = g_zx[zxb + ((size_t)(f + 2 * F_) << 12)] + g_zs[zsb + ((size_t)(f + 2 * F_) << 12)];
            float zo = g_zx[zxb + ((size_t)(f + 3 * F_) << 12)] + g_zs[zsb + ((size_t)(f + 3 * F_) << 12)];

            float ig = __saturatef(fmaf(0.2f, zi, 0.5f));
            float fg2 = __saturatef(fmaf(0.2f, zf, 0.5f));
            float og = __saturatef(fmaf(0.2f, zo, 0.5f));

            float cold = g_c[cb + ((size_t)f << 12)];
            float cnew = fmaf(fg2, cold, ig * tanhf(zc));
            float h    = og * tanhf(cnew);

            g_c[cb + ((size_t)f << 12)] = cnew;
            g_h[cb + ((size_t)f << 12)] = h;
            sh[f * 65 + pl] = h;
        }
    }
    __syncthreads();
    {
        int fq  = tid & 3;                       // f-quarter in low bits
        int pl2 = tid >> 2;                      // 0..63
        float* op = out + (((size_t)frame << 12) + pixbase + pl2) * F_ + fq * 16;
        #pragma unroll
        for (int j = 0; j < 4; j++) {            // 4 float4 per thread
            float4 o = *(float4*)(op + j * 4);
            int f = fq * 16 + j * 4;
            o.x += sh[(f    ) * 65 + pl2];
            o.y += sh[(f + 1) * 65 + pl2];
            o.z += sh[(f + 2) * 65 + pl2];
            o.w += sh[(f + 3) * 65 + pl2];
            *(float4*)(op + j * 4) = o;
        }
    }
}

// ---------------------------------------------------------------------------
extern "C" void kernel_launch(void* const* d_in, const int* in_sizes, int n_in,
                              void* d_out, int out_size) {
    const float* x  = (const float*)d_in[0];
    const float* Wx = (const float*)d_in[1];
    const float* Wh = (const float*)d_in[2];
    const float* b  = (const float*)d_in[3];
    const float* Wp = (const float*)d_in[4];
    const float* bp = (const float*)d_in[5];
    float* out = (float*)d_out;

    cudaFuncSetAttribute(conv3x3_kernel<CIN_X, 0>,
                         cudaFuncAttributeMaxDynamicSharedMemorySize, SMEM_CONV);
    cudaFuncSetAttribute(conv3x3_kernel<F_, 1>,
                         cudaFuncAttributeMaxDynamicSharedMemorySize, SMEM_CONV);

    // side stream + events for overlap (host handles only; no device memory)
    cudaStream_t s1;
    cudaStreamCreateWithFlags(&s1, cudaStreamNonBlocking);
    cudaEvent_t ev[T_], evJoin;
    for (int t = 0; t < T_; t++) cudaEventCreateWithFlags(&ev[t], cudaEventDisableTiming);
    cudaEventCreateWithFlags(&evJoin, cudaEventDisableTiming);

    // main stream (0): state reset, pack, residual, then per-t x-conv slices
    zero_hc_kernel<<<(B_ * F_ * HW + 255) / 256, 256>>>();
    pack_x_kernel<<<dim3(16, FRAMES), 256>>>(x);
    residual_kernel<<<(FRAMES * HW) / 256, 256>>>(x, Wp, bp, out);

    for (int t = 0; t < T_; t++) {
        conv3x3_kernel<CIN_X, 0><<<dim3(4, B_, 8), 256, SMEM_CONV>>>(Wx, b, t);
        cudaEventRecord(ev[t], 0);
    }

    // side stream: recurrent chain, step t gated on its zx slice
    for (int t = 0; t < T_; t++) {
        cudaStreamWaitEvent(s1, ev[t], 0);
        conv3x3_kernel<F_, 1><<<dim3(4, B_, 8), 256, SMEM_CONV, s1>>>(Wh, nullptr, t);
        gate_kernel<<<256, 256, 0, s1>>>(out, t);
    }

    // join back to main stream
    cudaEventRecord(evJoin, s1);
    cudaStreamWaitEvent(0, evJoin, 0);
}